// round 1
// baseline (speedup 1.0000x reference)
#include <cuda_runtime.h>
#include <math.h>

#define B_ 2
#define T_ 2048
#define C_ 1024
#define H_ 16
#define D_ 64

// Scratch (allocation-free rule: __device__ globals)
__device__ float g_q[(size_t)B_*H_*T_*D_];
__device__ float g_k[(size_t)B_*H_*T_*D_];
__device__ float g_v[(size_t)B_*H_*T_*D_];
__device__ float g_att[(size_t)B_*T_*C_];

// ---------------------------------------------------------------------------
// GEMM: Y = X @ W^T.  X:[M,K] row-major, W:[N,K] row-major.
// BM=128, BN=64, BK=16, 256 threads, 8x4 outputs/thread.
// MODE 0: Y row-major [M,N].  MODE 1: Y in [B,H,T,D] layout (n0 tile == one head).
// ---------------------------------------------------------------------------
template <int MODE>
__global__ __launch_bounds__(256)
void gemm_xwt(const float* __restrict__ X, const float* __restrict__ W,
              float* __restrict__ Y, int M, int N, int K)
{
    __shared__ __align__(16) float Xs[16][128 + 4];
    __shared__ __align__(16) float Ws[16][64 + 4];

    const int tid = threadIdx.x;
    const int m0 = blockIdx.y * 128;
    const int n0 = blockIdx.x * 64;
    const int ty = tid >> 4;   // 0..15
    const int tx = tid & 15;   // 0..15

    float acc[8][4];
#pragma unroll
    for (int i = 0; i < 8; i++)
#pragma unroll
        for (int j = 0; j < 4; j++) acc[i][j] = 0.f;

    for (int k0 = 0; k0 < K; k0 += 16) {
        // Stage X tile (128x16) transposed: 512 float4, 2 per thread.
#pragma unroll
        for (int li = 0; li < 2; li++) {
            int f  = tid + li * 256;
            int r  = f >> 2;
            int c4 = f & 3;
            float4 v = *(const float4*)(X + (size_t)(m0 + r) * K + k0 + c4 * 4);
            Xs[c4 * 4 + 0][r] = v.x;
            Xs[c4 * 4 + 1][r] = v.y;
            Xs[c4 * 4 + 2][r] = v.z;
            Xs[c4 * 4 + 3][r] = v.w;
        }
        // Stage W tile (64x16) transposed: 256 float4, 1 per thread.
        {
            int r  = tid >> 2;
            int c4 = tid & 3;
            float4 v = *(const float4*)(W + (size_t)(n0 + r) * K + k0 + c4 * 4);
            Ws[c4 * 4 + 0][r] = v.x;
            Ws[c4 * 4 + 1][r] = v.y;
            Ws[c4 * 4 + 2][r] = v.z;
            Ws[c4 * 4 + 3][r] = v.w;
        }
        __syncthreads();

#pragma unroll
        for (int kk = 0; kk < 16; kk++) {
            float a[8], b[4];
            float4 a0 = *(const float4*)&Xs[kk][ty * 8];
            float4 a1 = *(const float4*)&Xs[kk][ty * 8 + 4];
            a[0]=a0.x; a[1]=a0.y; a[2]=a0.z; a[3]=a0.w;
            a[4]=a1.x; a[5]=a1.y; a[6]=a1.z; a[7]=a1.w;
            float4 b0 = *(const float4*)&Ws[kk][tx * 4];
            b[0]=b0.x; b[1]=b0.y; b[2]=b0.z; b[3]=b0.w;
#pragma unroll
            for (int i = 0; i < 8; i++)
#pragma unroll
                for (int j = 0; j < 4; j++) acc[i][j] += a[i] * b[j];
        }
        __syncthreads();
    }

#pragma unroll
    for (int i = 0; i < 8; i++) {
        int row = m0 + ty * 8 + i;
        int col = n0 + tx * 4;
        float4 v = make_float4(acc[i][0], acc[i][1], acc[i][2], acc[i][3]);
        if (MODE == 0) {
            *(float4*)(Y + (size_t)row * N + col) = v;
        } else {
            int b = row >> 11;          // row / T_
            int t = row & (T_ - 1);
            int h = col >> 6;           // col / D_
            int d = col & (D_ - 1);
            *(float4*)(Y + (((size_t)b * H_ + h) * T_ + t) * D_ + d) = v;
        }
    }
}

// ---------------------------------------------------------------------------
// RoPE: in-place on q and k, one thread per (b,h,t) row (owns both halves).
// inv_freq[i] = 10000^(-i/32) = 2^(-i * log2(10000)/32)
// ---------------------------------------------------------------------------
__global__ __launch_bounds__(128)
void rope_kernel(float* __restrict__ q, float* __restrict__ k)
{
    int idx = blockIdx.x * blockDim.x + threadIdx.x;  // (b*H+h)*T + t
    if (idx >= B_ * H_ * T_) return;
    int t = idx & (T_ - 1);

    float cs[32], sn[32];
#pragma unroll
    for (int i = 0; i < 32; i++) {
        float invf = exp2f(-0.4152410118609203f * (float)i);
        float ang = (float)t * invf;
        sincosf(ang, &sn[i], &cs[i]);
    }

    float* rows[2] = { q + (size_t)idx * D_, k + (size_t)idx * D_ };
#pragma unroll
    for (int a = 0; a < 2; a++) {
        float* r = rows[a];
        float v[64];
#pragma unroll
        for (int i = 0; i < 16; i++) ((float4*)v)[i] = ((const float4*)r)[i];
#pragma unroll
        for (int i = 0; i < 32; i++) {
            float lo = v[i], hi = v[i + 32];
            v[i]      = lo * cs[i] - hi * sn[i];
            v[i + 32] = hi * cs[i] + lo * sn[i];
        }
#pragma unroll
        for (int i = 0; i < 16; i++) ((float4*)r)[i] = ((float4*)v)[i];
    }
}

// ---------------------------------------------------------------------------
// Causal flash attention, fp32.
// grid (B*H, T/128), 128 threads/block; thread = one query row.
// smem: K tile 64x64, V tile 64x64, scores 128x65 (padded).
// ---------------------------------------------------------------------------
__global__ __launch_bounds__(128)
void attn_kernel()
{
    extern __shared__ float smem[];
    float* Ksh = smem;                 // 4096
    float* Vsh = smem + 4096;          // 4096
    float* Ssh = smem + 8192;          // 128*65

    const int bh = blockIdx.x;         // 0..B*H-1
    const int qt = blockIdx.y;         // 0..15
    const int r  = threadIdx.x;        // 0..127
    const int qi = qt * 128 + r;

    const float* qrow = g_q + ((size_t)bh * T_ + qi) * D_;
    float qreg[64];
#pragma unroll
    for (int i = 0; i < 16; i++) ((float4*)qreg)[i] = ((const float4*)qrow)[i];
#pragma unroll
    for (int d = 0; d < 64; d++) qreg[d] *= 0.125f;   // 1/sqrt(64)

    float acc[64];
#pragma unroll
    for (int d = 0; d < 64; d++) acc[d] = 0.f;
    float m = -INFINITY, l = 0.f;
    float* Srow = Ssh + r * 65;

    const float* Kbase = g_k + (size_t)bh * T_ * D_;
    const float* Vbase = g_v + (size_t)bh * T_ * D_;
    const int nkt = qt * 2 + 2;        // causal: only tiles with keys <= qi_max

    for (int kt = 0; kt < nkt; kt++) {
        __syncthreads();
        {   // stage K,V 64x64 tiles: 2 threads per row, 8 float4 each
            int rr = r >> 1;
            int cc = (r & 1) * 32;
            const float* kg = Kbase + ((size_t)(kt * 64 + rr)) * D_ + cc;
            const float* vg = Vbase + ((size_t)(kt * 64 + rr)) * D_ + cc;
            float* ks = Ksh + rr * 64 + cc;
            float* vs = Vsh + rr * 64 + cc;
#pragma unroll
            for (int i = 0; i < 8; i++) {
                ((float4*)ks)[i] = ((const float4*)kg)[i];
                ((float4*)vs)[i] = ((const float4*)vg)[i];
            }
        }
        __syncthreads();

        const int kbase = kt * 64;
        if (qi >= kbase) {
            const int jmax = qi - kbase;       // valid keys: j <= min(jmax,63)
            float tmax = -INFINITY;
            for (int j = 0; j < 64; j++) {
                float s = -INFINITY;
                if (j <= jmax) {
                    const float4* k4 = (const float4*)(Ksh + j * 64);
                    float s0 = 0.f, s1 = 0.f, s2 = 0.f, s3 = 0.f;
#pragma unroll
                    for (int i = 0; i < 16; i++) {
                        float4 kv = k4[i];
                        float4 qv = ((const float4*)qreg)[i];
                        s0 += qv.x * kv.x; s1 += qv.y * kv.y;
                        s2 += qv.z * kv.z; s3 += qv.w * kv.w;
                    }
                    s = (s0 + s1) + (s2 + s3);
                    tmax = fmaxf(tmax, s);
                }
                Srow[j] = s;
            }
            float mnew  = fmaxf(m, tmax);
            float scale = __expf(m - mnew);    // m=-inf -> 0 (zeroes acc correctly)
#pragma unroll
            for (int d = 0; d < 64; d++) acc[d] *= scale;

            float psum = 0.f;
            const int jend = (jmax < 63) ? (jmax + 1) : 64;
            for (int j = 0; j < jend; j++) {
                float p = __expf(Srow[j] - mnew);
                psum += p;
                const float4* v4 = (const float4*)(Vsh + j * 64);
#pragma unroll
                for (int i = 0; i < 16; i++) {
                    float4 vv = v4[i];
                    acc[i * 4 + 0] += p * vv.x;
                    acc[i * 4 + 1] += p * vv.y;
                    acc[i * 4 + 2] += p * vv.z;
                    acc[i * 4 + 3] += p * vv.w;
                }
            }
            l = l * scale + psum;
            m = mnew;
        }
    }

    const float inv = 1.f / l;
    const int b = bh >> 4, h = bh & (H_ - 1);
    float* out = g_att + (((size_t)b * T_ + qi) * C_ + h * D_);
#pragma unroll
    for (int i = 0; i < 16; i++) {
        float4 v;
        v.x = acc[i * 4 + 0] * inv;
        v.y = acc[i * 4 + 1] * inv;
        v.z = acc[i * 4 + 2] * inv;
        v.w = acc[i * 4 + 3] * inv;
        ((float4*)out)[i] = v;
    }
}

// ---------------------------------------------------------------------------
extern "C" void kernel_launch(void* const* d_in, const int* in_sizes, int n_in,
                              void* d_out, int out_size)
{
    const float* x  = (const float*)d_in[0];
    const float* Wq = (const float*)d_in[1];
    const float* Wk = (const float*)d_in[2];
    const float* Wv = (const float*)d_in[3];
    const float* Wo = (const float*)d_in[4];
    float* out = (float*)d_out;

    float *q, *k, *v, *att;
    cudaGetSymbolAddress((void**)&q,   g_q);
    cudaGetSymbolAddress((void**)&k,   g_k);
    cudaGetSymbolAddress((void**)&v,   g_v);
    cudaGetSymbolAddress((void**)&att, g_att);

    const int M = B_ * T_;
    dim3 gg(C_ / 64, M / 128);

    gemm_xwt<1><<<gg, 256>>>(x, Wq, q, M, C_, C_);
    gemm_xwt<1><<<gg, 256>>>(x, Wk, k, M, C_, C_);
    gemm_xwt<1><<<gg, 256>>>(x, Wv, v, M, C_, C_);

    rope_kernel<<<(B_ * H_ * T_) / 128, 128>>>(q, k);

    size_t smem = (size_t)(4096 + 4096 + 128 * 65) * sizeof(float);  // 66048 B
    cudaFuncSetAttribute(attn_kernel, cudaFuncAttributeMaxDynamicSharedMemorySize, (int)smem);
    attn_kernel<<<dim3(B_ * H_, T_ / 128), 128, smem>>>();

    gemm_xwt<0><<<gg, 256>>>(att, Wo, out, M, C_, C_);
}

// round 3
// speedup vs baseline: 1.7181x; 1.7181x over previous
#include <cuda_runtime.h>
#include <cuda_fp16.h>
#include <math.h>
#include <stdint.h>

#define B_ 2
#define T_ 2048
#define C_ 1024
#define H_ 16
#define D_ 64

// Scratch (allocation-free rule: __device__ globals)
__device__ float  g_q[(size_t)B_*H_*T_*D_];
__device__ float  g_k[(size_t)B_*H_*T_*D_];
__device__ float  g_v[(size_t)B_*H_*T_*D_];
__device__ float  g_att[(size_t)B_*T_*C_];
__device__ __half g_xh[(size_t)B_*T_*C_];   // fp16 activations (x, later att)
__device__ __half g_wh[(size_t)C_*C_];      // fp16 staging for current weight

// ---------------------------------------------------------------------------
// fp32 -> fp16 conversion (vectorized)
// ---------------------------------------------------------------------------
__global__ __launch_bounds__(256)
void f2h_kernel(const float* __restrict__ src, __half* __restrict__ dst, int n)
{
    int i = (blockIdx.x * 256 + threadIdx.x) * 4;
    if (i < n) {
        float4 v = *(const float4*)(src + i);
        __half2 a = __floats2half2_rn(v.x, v.y);
        __half2 b = __floats2half2_rn(v.z, v.w);
        uint2 o;
        o.x = *(uint32_t*)&a;
        o.y = *(uint32_t*)&b;
        *(uint2*)(dst + i) = o;
    }
}

// ---------------------------------------------------------------------------
// HMMA GEMM: Y = Xh @ Wh^T, fp16 in, fp32 accum.
// Xh:[M,K] row-major, Wh:[N,K] row-major (both K-major == mma row.col layout).
// CTA 128x128, BK=32, 256 threads = 8 warps (4 m-rows x 2 n-cols),
// warp tile 32x64. cp.async double-buffered smem, pad-8 rows (stride 40 halves).
// MODE 0: Y row-major [M,N].  MODE 1: Y in [B,H,T,D].
// ---------------------------------------------------------------------------
#define BK 32
#define SSTR 40   // smem row stride in halves (conflict-free for ldmatrix)

__device__ __forceinline__ void cp_async16(uint32_t dst, const void* src) {
    asm volatile("cp.async.ca.shared.global [%0], [%1], 16;" :: "r"(dst), "l"(src));
}
__device__ __forceinline__ void ldmatrix_x4(uint32_t& r0, uint32_t& r1,
                                            uint32_t& r2, uint32_t& r3, uint32_t a) {
    asm volatile("ldmatrix.sync.aligned.m8n8.x4.shared.b16 {%0,%1,%2,%3}, [%4];"
                 : "=r"(r0), "=r"(r1), "=r"(r2), "=r"(r3) : "r"(a));
}
__device__ __forceinline__ void mma16816(float* d, const uint32_t* a, const uint32_t* b) {
    asm volatile("mma.sync.aligned.m16n8k16.row.col.f32.f16.f16.f32 "
                 "{%0,%1,%2,%3}, {%4,%5,%6,%7}, {%8,%9}, {%0,%1,%2,%3};"
                 : "+f"(d[0]), "+f"(d[1]), "+f"(d[2]), "+f"(d[3])
                 : "r"(a[0]), "r"(a[1]), "r"(a[2]), "r"(a[3]), "r"(b[0]), "r"(b[1]));
}

template <int MODE>
__global__ __launch_bounds__(256)
void gemm_mma(const __half* __restrict__ Xh, const __half* __restrict__ Wh,
              float* __restrict__ Y, int M, int N, int K)
{
    __shared__ __align__(16) __half As[2][128][SSTR];
    __shared__ __align__(16) __half Bs[2][128][SSTR];

    const int tid  = threadIdx.x;
    const int wid  = tid >> 5;
    const int lane = tid & 31;
    const int m0 = blockIdx.y * 128;
    const int n0 = blockIdx.x * 128;
    const int wm = (wid & 3) * 32;   // warp m origin in tile
    const int wn = (wid >> 2) * 64;  // warp n origin in tile

    float acc[2][8][4];
#pragma unroll
    for (int i = 0; i < 2; i++)
#pragma unroll
        for (int j = 0; j < 8; j++)
#pragma unroll
            for (int c = 0; c < 4; c++) acc[i][j][c] = 0.f;

    // stage loader: A/B each 128 rows x 32 halves = 512 16B chunks; 2 per thread each
    auto issue_stage = [&](int s, int k0) {
#pragma unroll
        for (int li = 0; li < 2; li++) {
            int c   = tid + li * 256;
            int row = c >> 2;
            int seg = (c & 3) * 8;
            uint32_t da = (uint32_t)__cvta_generic_to_shared(&As[s][row][seg]);
            uint32_t db = (uint32_t)__cvta_generic_to_shared(&Bs[s][row][seg]);
            cp_async16(da, Xh + (size_t)(m0 + row) * K + k0 + seg);
            cp_async16(db, Wh + (size_t)(n0 + row) * K + k0 + seg);
        }
        asm volatile("cp.async.commit_group;");
    };

    const int NT = K / BK;
    issue_stage(0, 0);

    for (int kt = 0; kt < NT; kt++) {
        const int s = kt & 1;
        if (kt + 1 < NT) {
            issue_stage(s ^ 1, (kt + 1) * BK);
            asm volatile("cp.async.wait_group 1;");
        } else {
            asm volatile("cp.async.wait_group 0;");
        }
        __syncthreads();

#pragma unroll
        for (int kk = 0; kk < 2; kk++) {        // two k16 steps per BK=32
            uint32_t af[2][4];
#pragma unroll
            for (int mi = 0; mi < 2; mi++) {
                uint32_t a = (uint32_t)__cvta_generic_to_shared(
                    &As[s][wm + mi * 16 + (lane & 15)][kk * 16 + ((lane >> 4) << 3)]);
                ldmatrix_x4(af[mi][0], af[mi][1], af[mi][2], af[mi][3], a);
            }
            uint32_t bf[8][2];
#pragma unroll
            for (int nb = 0; nb < 4; nb++) {    // each x4 covers two n8 blocks
                uint32_t r0, r1, r2, r3;
                uint32_t a = (uint32_t)__cvta_generic_to_shared(
                    &Bs[s][wn + nb * 16 + (lane & 7) + ((lane >> 4) << 3)]
                        [kk * 16 + ((lane >> 3) & 1) * 8]);
                ldmatrix_x4(r0, r1, r2, r3, a);
                bf[nb * 2 + 0][0] = r0; bf[nb * 2 + 0][1] = r1;
                bf[nb * 2 + 1][0] = r2; bf[nb * 2 + 1][1] = r3;
            }
#pragma unroll
            for (int mi = 0; mi < 2; mi++)
#pragma unroll
                for (int ni = 0; ni < 8; ni++)
                    mma16816(acc[mi][ni], af[mi], bf[ni]);
        }
        __syncthreads();
    }

    // Epilogue. D frag: rows (lane>>2)+{0,8}, cols (lane&3)*2+{0,1}
#pragma unroll
    for (int mi = 0; mi < 2; mi++) {
#pragma unroll
        for (int ni = 0; ni < 8; ni++) {
#pragma unroll
            for (int half_ = 0; half_ < 2; half_++) {
                int row = m0 + wm + mi * 16 + (lane >> 2) + half_ * 8;
                int col = n0 + wn + ni * 8 + (lane & 3) * 2;
                float2 v = make_float2(acc[mi][ni][half_ * 2], acc[mi][ni][half_ * 2 + 1]);
                if (MODE == 0) {
                    *(float2*)(Y + (size_t)row * N + col) = v;
                } else {
                    int b = row >> 11;
                    int t = row & (T_ - 1);
                    int h = col >> 6;
                    int d = col & (D_ - 1);
                    *(float2*)(Y + (((size_t)b * H_ + h) * T_ + t) * D_ + d) = v;
                }
            }
        }
    }
}

// ---------------------------------------------------------------------------
// RoPE: one warp per (b,h,t) row; lane i owns pair (i, i+32).
// ---------------------------------------------------------------------------
__global__ __launch_bounds__(256)
void rope_kernel(float* __restrict__ q, float* __restrict__ k)
{
    int w    = blockIdx.x * 8 + (threadIdx.x >> 5);
    int lane = threadIdx.x & 31;
    int t    = w & (T_ - 1);

    float invf = exp2f(-0.4152410118609203f * (float)lane);
    float sn, cs;
    sincosf((float)t * invf, &sn, &cs);

    float* qr = q + (size_t)w * D_;
    float* kr = k + (size_t)w * D_;
    float qlo = qr[lane], qhi = qr[lane + 32];
    float klo = kr[lane], khi = kr[lane + 32];
    qr[lane]      = qlo * cs - qhi * sn;
    qr[lane + 32] = qhi * cs + qlo * sn;
    kr[lane]      = klo * cs - khi * sn;
    kr[lane + 32] = khi * cs + klo * sn;
}

// ---------------------------------------------------------------------------
// Causal flash attention, fp32.
// grid (B*H, T/128), 128 threads/block; thread = one query row.
// ---------------------------------------------------------------------------
__global__ __launch_bounds__(128)
void attn_kernel()
{
    extern __shared__ float smem_f[];
    float* Ksh = smem_f;
    float* Vsh = smem_f + 4096;
    float* Ssh = smem_f + 8192;

    const int bh = blockIdx.x;
    const int qt = blockIdx.y;
    const int r  = threadIdx.x;
    const int qi = qt * 128 + r;

    const float* qrow = g_q + ((size_t)bh * T_ + qi) * D_;
    float qreg[64];
#pragma unroll
    for (int i = 0; i < 16; i++) ((float4*)qreg)[i] = ((const float4*)qrow)[i];
#pragma unroll
    for (int d = 0; d < 64; d++) qreg[d] *= 0.125f;

    float acc[64];
#pragma unroll
    for (int d = 0; d < 64; d++) acc[d] = 0.f;
    float m = -INFINITY, l = 0.f;
    float* Srow = Ssh + r * 65;

    const float* Kbase = g_k + (size_t)bh * T_ * D_;
    const float* Vbase = g_v + (size_t)bh * T_ * D_;
    const int nkt = qt * 2 + 2;

    for (int kt = 0; kt < nkt; kt++) {
        __syncthreads();
        {
            int rr = r >> 1;
            int cc = (r & 1) * 32;
            const float* kg = Kbase + ((size_t)(kt * 64 + rr)) * D_ + cc;
            const float* vg = Vbase + ((size_t)(kt * 64 + rr)) * D_ + cc;
            float* ks = Ksh + rr * 64 + cc;
            float* vs = Vsh + rr * 64 + cc;
#pragma unroll
            for (int i = 0; i < 8; i++) {
                ((float4*)ks)[i] = ((const float4*)kg)[i];
                ((float4*)vs)[i] = ((const float4*)vg)[i];
            }
        }
        __syncthreads();

        const int kbase = kt * 64;
        if (qi >= kbase) {
            const int jmax = qi - kbase;
            float tmax = -INFINITY;
            for (int j = 0; j < 64; j++) {
                float s = -INFINITY;
                if (j <= jmax) {
                    const float4* k4 = (const float4*)(Ksh + j * 64);
                    float s0 = 0.f, s1 = 0.f, s2 = 0.f, s3 = 0.f;
#pragma unroll
                    for (int i = 0; i < 16; i++) {
                        float4 kv = k4[i];
                        float4 qv = ((const float4*)qreg)[i];
                        s0 += qv.x * kv.x; s1 += qv.y * kv.y;
                        s2 += qv.z * kv.z; s3 += qv.w * kv.w;
                    }
                    s = (s0 + s1) + (s2 + s3);
                    tmax = fmaxf(tmax, s);
                }
                Srow[j] = s;
            }
            float mnew  = fmaxf(m, tmax);
            float scale = __expf(m - mnew);
#pragma unroll
            for (int d = 0; d < 64; d++) acc[d] *= scale;

            float psum = 0.f;
            const int jend = (jmax < 63) ? (jmax + 1) : 64;
            for (int j = 0; j < jend; j++) {
                float p = __expf(Srow[j] - mnew);
                psum += p;
                const float4* v4 = (const float4*)(Vsh + j * 64);
#pragma unroll
                for (int i = 0; i < 16; i++) {
                    float4 vv = v4[i];
                    acc[i * 4 + 0] += p * vv.x;
                    acc[i * 4 + 1] += p * vv.y;
                    acc[i * 4 + 2] += p * vv.z;
                    acc[i * 4 + 3] += p * vv.w;
                }
            }
            l = l * scale + psum;
            m = mnew;
        }
    }

    const float inv = 1.f / l;
    const int b = bh >> 4, h = bh & (H_ - 1);
    float* out = g_att + (((size_t)b * T_ + qi) * C_ + h * D_);
#pragma unroll
    for (int i = 0; i < 16; i++) {
        float4 v;
        v.x = acc[i * 4 + 0] * inv;
        v.y = acc[i * 4 + 1] * inv;
        v.z = acc[i * 4 + 2] * inv;
        v.w = acc[i * 4 + 3] * inv;
        ((float4*)out)[i] = v;
    }
}

// ---------------------------------------------------------------------------
extern "C" void kernel_launch(void* const* d_in, const int* in_sizes, int n_in,
                              void* d_out, int out_size)
{
    const float* x  = (const float*)d_in[0];
    const float* Wq = (const float*)d_in[1];
    const float* Wk = (const float*)d_in[2];
    const float* Wv = (const float*)d_in[3];
    const float* Wo = (const float*)d_in[4];
    float* out = (float*)d_out;

    float *q, *k, *v, *att;
    __half *xh, *wh;
    cudaGetSymbolAddress((void**)&q,   g_q);
    cudaGetSymbolAddress((void**)&k,   g_k);
    cudaGetSymbolAddress((void**)&v,   g_v);
    cudaGetSymbolAddress((void**)&att, g_att);
    cudaGetSymbolAddress((void**)&xh,  g_xh);
    cudaGetSymbolAddress((void**)&wh,  g_wh);

    const int M = B_ * T_;   // 4096
    const int NWX = (M * C_) / (256 * 4);
    const int NWW = (C_ * C_) / (256 * 4);

    dim3 gg(C_ / 128, M / 128);   // (8, 32)

    f2h_kernel<<<NWX, 256>>>(x, xh, M * C_);
    f2h_kernel<<<NWW, 256>>>(Wq, wh, C_ * C_);
    gemm_mma<1><<<gg, 256>>>(xh, wh, q, M, C_, C_);
    f2h_kernel<<<NWW, 256>>>(Wk, wh, C_ * C_);
    gemm_mma<1><<<gg, 256>>>(xh, wh, k, M, C_, C_);
    f2h_kernel<<<NWW, 256>>>(Wv, wh, C_ * C_);
    gemm_mma<1><<<gg, 256>>>(xh, wh, v, M, C_, C_);

    rope_kernel<<<(B_ * H_ * T_) / 8, 256>>>(q, k);

    size_t smem = (size_t)(4096 + 4096 + 128 * 65) * sizeof(float);
    cudaFuncSetAttribute(attn_kernel, cudaFuncAttributeMaxDynamicSharedMemorySize, (int)smem);
    attn_kernel<<<dim3(B_ * H_, T_ / 128), 128, smem>>>();

    f2h_kernel<<<NWX, 256>>>(att, xh, M * C_);
    f2h_kernel<<<NWW, 256>>>(Wo, wh, C_ * C_);
    gemm_mma<0><<<gg, 256>>>(xh, wh, out, M, C_, C_);
}

// round 4
// speedup vs baseline: 8.0617x; 4.6921x over previous
#include <cuda_runtime.h>
#include <cuda_fp16.h>
#include <math.h>
#include <stdint.h>

#define B_ 2
#define T_ 2048
#define C_ 1024
#define H_ 16
#define D_ 64

// Scratch (allocation-free rule: __device__ globals)
__device__ float  g_q[(size_t)B_*H_*T_*D_];
__device__ float  g_k[(size_t)B_*H_*T_*D_];
__device__ float  g_att[(size_t)B_*T_*C_];
__device__ __half g_xh[(size_t)B_*T_*C_];   // fp16 activations (x, later att)
__device__ __half g_wh[(size_t)C_*C_];      // fp16 staging for current weight
__device__ __half g_qh[(size_t)B_*H_*T_*D_];
__device__ __half g_kh[(size_t)B_*H_*T_*D_];
__device__ __half g_vh[(size_t)B_*H_*T_*D_];

// ---------------------------------------------------------------------------
// common helpers
// ---------------------------------------------------------------------------
__device__ __forceinline__ void cp_async16(uint32_t dst, const void* src) {
    asm volatile("cp.async.ca.shared.global [%0], [%1], 16;" :: "r"(dst), "l"(src));
}
__device__ __forceinline__ void ldmatrix_x4(uint32_t& r0, uint32_t& r1,
                                            uint32_t& r2, uint32_t& r3, uint32_t a) {
    asm volatile("ldmatrix.sync.aligned.m8n8.x4.shared.b16 {%0,%1,%2,%3}, [%4];"
                 : "=r"(r0), "=r"(r1), "=r"(r2), "=r"(r3) : "r"(a));
}
__device__ __forceinline__ void ldmatrix_x4_t(uint32_t& r0, uint32_t& r1,
                                              uint32_t& r2, uint32_t& r3, uint32_t a) {
    asm volatile("ldmatrix.sync.aligned.m8n8.x4.trans.shared.b16 {%0,%1,%2,%3}, [%4];"
                 : "=r"(r0), "=r"(r1), "=r"(r2), "=r"(r3) : "r"(a));
}
__device__ __forceinline__ void mma16816(float* d, const uint32_t* a, const uint32_t* b) {
    asm volatile("mma.sync.aligned.m16n8k16.row.col.f32.f16.f16.f32 "
                 "{%0,%1,%2,%3}, {%4,%5,%6,%7}, {%8,%9}, {%0,%1,%2,%3};"
                 : "+f"(d[0]), "+f"(d[1]), "+f"(d[2]), "+f"(d[3])
                 : "r"(a[0]), "r"(a[1]), "r"(a[2]), "r"(a[3]), "r"(b[0]), "r"(b[1]));
}
__device__ __forceinline__ uint32_t pack_h2(float a, float b) {
    __half2 h = __floats2half2_rn(a, b);
    return *(uint32_t*)&h;
}

// ---------------------------------------------------------------------------
// fp32 -> fp16 conversion
// ---------------------------------------------------------------------------
__global__ __launch_bounds__(256)
void f2h_kernel(const float* __restrict__ src, __half* __restrict__ dst, int n)
{
    int i = (blockIdx.x * 256 + threadIdx.x) * 4;
    if (i < n) {
        float4 v = *(const float4*)(src + i);
        __half2 a = __floats2half2_rn(v.x, v.y);
        __half2 b = __floats2half2_rn(v.z, v.w);
        uint2 o;
        o.x = *(uint32_t*)&a;
        o.y = *(uint32_t*)&b;
        *(uint2*)(dst + i) = o;
    }
}

// ---------------------------------------------------------------------------
// HMMA GEMM: Y = Xh @ Wh^T. CTA 128x128, BK=32, 8 warps, warp tile 32x64.
// MODE 0: fp32 row-major [M,N].  MODE 1: fp32 [B,H,T,D].  MODE 2: fp16 [B,H,T,D].
// ---------------------------------------------------------------------------
#define BK 32
#define SSTR 40

template <int MODE>
__global__ __launch_bounds__(256)
void gemm_mma(const __half* __restrict__ Xh, const __half* __restrict__ Wh,
              float* __restrict__ Y, int M, int N, int K)
{
    __shared__ __align__(16) __half As[2][128][SSTR];
    __shared__ __align__(16) __half Bs[2][128][SSTR];

    const int tid  = threadIdx.x;
    const int wid  = tid >> 5;
    const int lane = tid & 31;
    const int m0 = blockIdx.y * 128;
    const int n0 = blockIdx.x * 128;
    const int wm = (wid & 3) * 32;
    const int wn = (wid >> 2) * 64;

    float acc[2][8][4];
#pragma unroll
    for (int i = 0; i < 2; i++)
#pragma unroll
        for (int j = 0; j < 8; j++)
#pragma unroll
            for (int c = 0; c < 4; c++) acc[i][j][c] = 0.f;

    auto issue_stage = [&](int s, int k0) {
#pragma unroll
        for (int li = 0; li < 2; li++) {
            int c   = tid + li * 256;
            int row = c >> 2;
            int seg = (c & 3) * 8;
            uint32_t da = (uint32_t)__cvta_generic_to_shared(&As[s][row][seg]);
            uint32_t db = (uint32_t)__cvta_generic_to_shared(&Bs[s][row][seg]);
            cp_async16(da, Xh + (size_t)(m0 + row) * K + k0 + seg);
            cp_async16(db, Wh + (size_t)(n0 + row) * K + k0 + seg);
        }
        asm volatile("cp.async.commit_group;");
    };

    const int NT = K / BK;
    issue_stage(0, 0);

    for (int kt = 0; kt < NT; kt++) {
        const int s = kt & 1;
        if (kt + 1 < NT) {
            issue_stage(s ^ 1, (kt + 1) * BK);
            asm volatile("cp.async.wait_group 1;");
        } else {
            asm volatile("cp.async.wait_group 0;");
        }
        __syncthreads();

#pragma unroll
        for (int kk = 0; kk < 2; kk++) {
            uint32_t af[2][4];
#pragma unroll
            for (int mi = 0; mi < 2; mi++) {
                uint32_t a = (uint32_t)__cvta_generic_to_shared(
                    &As[s][wm + mi * 16 + (lane & 15)][kk * 16 + ((lane >> 4) << 3)]);
                ldmatrix_x4(af[mi][0], af[mi][1], af[mi][2], af[mi][3], a);
            }
            uint32_t bf[8][2];
#pragma unroll
            for (int nb = 0; nb < 4; nb++) {
                uint32_t r0, r1, r2, r3;
                uint32_t a = (uint32_t)__cvta_generic_to_shared(
                    &Bs[s][wn + nb * 16 + (lane & 7) + ((lane >> 4) << 3)]
                        [kk * 16 + ((lane >> 3) & 1) * 8]);
                ldmatrix_x4(r0, r1, r2, r3, a);
                bf[nb * 2 + 0][0] = r0; bf[nb * 2 + 0][1] = r1;
                bf[nb * 2 + 1][0] = r2; bf[nb * 2 + 1][1] = r3;
            }
#pragma unroll
            for (int mi = 0; mi < 2; mi++)
#pragma unroll
                for (int ni = 0; ni < 8; ni++)
                    mma16816(acc[mi][ni], af[mi], bf[ni]);
        }
        __syncthreads();
    }

#pragma unroll
    for (int mi = 0; mi < 2; mi++) {
#pragma unroll
        for (int ni = 0; ni < 8; ni++) {
#pragma unroll
            for (int half_ = 0; half_ < 2; half_++) {
                int row = m0 + wm + mi * 16 + (lane >> 2) + half_ * 8;
                int col = n0 + wn + ni * 8 + (lane & 3) * 2;
                float v0 = acc[mi][ni][half_ * 2], v1 = acc[mi][ni][half_ * 2 + 1];
                if (MODE == 0) {
                    *(float2*)(Y + (size_t)row * N + col) = make_float2(v0, v1);
                } else {
                    int b = row >> 11;
                    int t = row & (T_ - 1);
                    int h = col >> 6;
                    int d = col & (D_ - 1);
                    size_t off = (((size_t)b * H_ + h) * T_ + t) * D_ + d;
                    if (MODE == 1) {
                        *(float2*)(Y + off) = make_float2(v0, v1);
                    } else {
                        *(uint32_t*)((__half*)Y + off) = pack_h2(v0, v1);
                    }
                }
            }
        }
    }
}

// ---------------------------------------------------------------------------
// RoPE: reads fp32 q,k; writes fp16 qh (pre-scaled by 1/8*log2e), kh.
// One warp per (b,h,t) row; lane i owns pair (i, i+32).
// ---------------------------------------------------------------------------
#define QSCALE 0.18033688011112042f   // 0.125 * log2(e)

__global__ __launch_bounds__(256)
void rope_kernel(const float* __restrict__ q, const float* __restrict__ k,
                 __half* __restrict__ qh, __half* __restrict__ kh)
{
    int w    = blockIdx.x * 8 + (threadIdx.x >> 5);
    int lane = threadIdx.x & 31;
    int t    = w & (T_ - 1);

    float invf = exp2f(-0.4152410118609203f * (float)lane);
    float sn, cs;
    sincosf((float)t * invf, &sn, &cs);

    const float* qr = q + (size_t)w * D_;
    const float* kr = k + (size_t)w * D_;
    float qlo = qr[lane], qhi = qr[lane + 32];
    float klo = kr[lane], khi = kr[lane + 32];
    __half* qo = qh + (size_t)w * D_;
    __half* ko = kh + (size_t)w * D_;
    qo[lane]      = __float2half((qlo * cs - qhi * sn) * QSCALE);
    qo[lane + 32] = __float2half((qhi * cs + qlo * sn) * QSCALE);
    ko[lane]      = __float2half(klo * cs - khi * sn);
    ko[lane + 32] = __float2half(khi * cs + klo * sn);
}

// ---------------------------------------------------------------------------
// Tensor-core causal flash attention (fp16 in, fp32 accum).
// CTA: 128 q-rows, 4 warps (32 rows each), KV tiles of 64.
// grid (B*H, T/128), 128 threads.
// ---------------------------------------------------------------------------
#define ATS 88   // smem row stride in halves: 176B, 16B-aligned, 12r%32 distinct

__global__ __launch_bounds__(128, 1)
void attn_mma()
{
    extern __shared__ __half ash[];
    __half (*Qs)[ATS] = (__half(*)[ATS])ash;                              // [128][ATS]
    __half (*Ks)[64][ATS] = (__half(*)[64][ATS])(ash + 128 * ATS);        // [2][64][ATS]
    __half (*Vs)[64][ATS] = (__half(*)[64][ATS])(ash + (128 + 2*64) * ATS);

    const int bh = blockIdx.x, qt = blockIdx.y;
    const int tid = threadIdx.x, wid = tid >> 5, lane = tid & 31;

    const __half* Qg = g_qh + ((size_t)bh * T_ + qt * 128) * D_;
    const __half* Kg = g_kh + (size_t)bh * T_ * D_;
    const __half* Vg = g_vh + (size_t)bh * T_ * D_;

    // Q tile -> smem
#pragma unroll
    for (int i = 0; i < 8; i++) {
        int c = tid + i * 128;
        int row = c >> 3, seg = c & 7;
        *(uint4*)&Qs[row][seg * 8] = *(const uint4*)(Qg + row * 64 + seg * 8);
    }
    __syncthreads();

    // Q fragments (held for whole kernel)
    uint32_t qa[2][4][4];
#pragma unroll
    for (int mi = 0; mi < 2; mi++)
#pragma unroll
        for (int t = 0; t < 4; t++) {
            uint32_t a = (uint32_t)__cvta_generic_to_shared(
                &Qs[wid * 32 + mi * 16 + ((lane >> 3) & 1) * 8 + (lane & 7)]
                   [t * 16 + (lane >> 4) * 8]);
            ldmatrix_x4(qa[mi][t][0], qa[mi][t][1], qa[mi][t][2], qa[mi][t][3], a);
        }

    float O[2][8][4];
#pragma unroll
    for (int mi = 0; mi < 2; mi++)
#pragma unroll
        for (int nj = 0; nj < 8; nj++)
#pragma unroll
            for (int c = 0; c < 4; c++) O[mi][nj][c] = 0.f;
    float mrow[2][2] = {{-INFINITY, -INFINITY}, {-INFINITY, -INFINITY}};
    float lrow[2][2] = {{0.f, 0.f}, {0.f, 0.f}};

    const int nkt = 2 * qt + 2;

    auto issue = [&](int s, int kt) {
#pragma unroll
        for (int i = 0; i < 8; i++) {
            int c = tid + i * 128;
            int isV = c >> 9, cc = c & 511, row = cc >> 3, seg = cc & 7;
            const __half* src = (isV ? Vg : Kg) + (size_t)(kt * 64 + row) * 64 + seg * 8;
            uint32_t dst = (uint32_t)__cvta_generic_to_shared(
                isV ? &Vs[s][row][seg * 8] : &Ks[s][row][seg * 8]);
            cp_async16(dst, src);
        }
        asm volatile("cp.async.commit_group;");
    };
    issue(0, 0);

    for (int kt = 0; kt < nkt; kt++) {
        const int s = kt & 1;
        if (kt + 1 < nkt) {
            issue(s ^ 1, kt + 1);
            asm volatile("cp.async.wait_group 1;");
        } else {
            asm volatile("cp.async.wait_group 0;");
        }
        __syncthreads();

        // warp entirely above diagonal? (no valid keys)
        bool active = (qt * 128 + wid * 32 + 31) >= kt * 64;
        if (active) {
            // ---- S = Q @ K^T ----
            float S[2][8][4];
#pragma unroll
            for (int mi = 0; mi < 2; mi++)
#pragma unroll
                for (int nj = 0; nj < 8; nj++)
#pragma unroll
                    for (int c = 0; c < 4; c++) S[mi][nj][c] = 0.f;

#pragma unroll
            for (int t = 0; t < 4; t++) {
                uint32_t bf[8][2];
#pragma unroll
                for (int jp = 0; jp < 4; jp++) {
                    uint32_t a = (uint32_t)__cvta_generic_to_shared(
                        &Ks[s][jp * 16 + ((lane >> 4) & 1) * 8 + (lane & 7)]
                            [t * 16 + ((lane >> 3) & 1) * 8]);
                    ldmatrix_x4(bf[2*jp][0], bf[2*jp][1], bf[2*jp+1][0], bf[2*jp+1][1], a);
                }
#pragma unroll
                for (int mi = 0; mi < 2; mi++)
#pragma unroll
                    for (int nj = 0; nj < 8; nj++)
                        mma16816(S[mi][nj], qa[mi][t], bf[nj]);
            }

            // ---- causal mask (only last two tiles can cross diagonal) ----
            if (kt >= 2 * qt) {
#pragma unroll
                for (int mi = 0; mi < 2; mi++)
#pragma unroll
                    for (int h = 0; h < 2; h++) {
                        int row = qt * 128 + wid * 32 + mi * 16 + (lane >> 2) + h * 8;
#pragma unroll
                        for (int nj = 0; nj < 8; nj++)
#pragma unroll
                            for (int e = 0; e < 2; e++) {
                                int key = kt * 64 + nj * 8 + (lane & 3) * 2 + e;
                                if (key > row) S[mi][nj][h * 2 + e] = -1e30f;
                            }
                    }
            }

            // ---- online softmax ----
            float al[2][2];
#pragma unroll
            for (int mi = 0; mi < 2; mi++)
#pragma unroll
                for (int h = 0; h < 2; h++) {
                    float rm = -1e30f;
#pragma unroll
                    for (int nj = 0; nj < 8; nj++)
                        rm = fmaxf(rm, fmaxf(S[mi][nj][h*2], S[mi][nj][h*2+1]));
                    rm = fmaxf(rm, __shfl_xor_sync(0xffffffffu, rm, 1));
                    rm = fmaxf(rm, __shfl_xor_sync(0xffffffffu, rm, 2));
                    float mn = fmaxf(mrow[mi][h], rm);
                    float alpha = exp2f(mrow[mi][h] - mn);
                    mrow[mi][h] = mn;
                    float ps = 0.f;
#pragma unroll
                    for (int nj = 0; nj < 8; nj++) {
                        float p0 = exp2f(S[mi][nj][h*2]   - mn);
                        float p1 = exp2f(S[mi][nj][h*2+1] - mn);
                        S[mi][nj][h*2]   = p0;
                        S[mi][nj][h*2+1] = p1;
                        ps += p0 + p1;
                    }
                    ps += __shfl_xor_sync(0xffffffffu, ps, 1);
                    ps += __shfl_xor_sync(0xffffffffu, ps, 2);
                    lrow[mi][h] = lrow[mi][h] * alpha + ps;
                    al[mi][h] = alpha;
                }
#pragma unroll
            for (int mi = 0; mi < 2; mi++)
#pragma unroll
                for (int nj = 0; nj < 8; nj++) {
                    O[mi][nj][0] *= al[mi][0];
                    O[mi][nj][1] *= al[mi][0];
                    O[mi][nj][2] *= al[mi][1];
                    O[mi][nj][3] *= al[mi][1];
                }

            // ---- O += P @ V ----
#pragma unroll
            for (int t = 0; t < 4; t++) {
                uint32_t bv[8][2];
#pragma unroll
                for (int jp = 0; jp < 4; jp++) {
                    uint32_t a = (uint32_t)__cvta_generic_to_shared(
                        &Vs[s][t * 16 + ((lane >> 3) & 1) * 8 + (lane & 7)]
                            [(2 * jp + ((lane >> 4) & 1)) * 8]);
                    ldmatrix_x4_t(bv[2*jp][0], bv[2*jp][1], bv[2*jp+1][0], bv[2*jp+1][1], a);
                }
#pragma unroll
                for (int mi = 0; mi < 2; mi++) {
                    uint32_t pa[4];
                    pa[0] = pack_h2(S[mi][2*t][0],   S[mi][2*t][1]);
                    pa[1] = pack_h2(S[mi][2*t][2],   S[mi][2*t][3]);
                    pa[2] = pack_h2(S[mi][2*t+1][0], S[mi][2*t+1][1]);
                    pa[3] = pack_h2(S[mi][2*t+1][2], S[mi][2*t+1][3]);
#pragma unroll
                    for (int nj = 0; nj < 8; nj++)
                        mma16816(O[mi][nj], pa, bv[nj]);
                }
            }
        }
        __syncthreads();
    }

    // ---- epilogue: normalize and store to [B,T,C] fp32 ----
    const int b = bh >> 4, hh = bh & (H_ - 1);
#pragma unroll
    for (int mi = 0; mi < 2; mi++)
#pragma unroll
        for (int h = 0; h < 2; h++) {
            float inv = 1.f / lrow[mi][h];
            int row = qt * 128 + wid * 32 + mi * 16 + (lane >> 2) + h * 8;
            float* dst = g_att + ((size_t)(b * T_ + row)) * C_ + hh * 64;
#pragma unroll
            for (int nj = 0; nj < 8; nj++) {
                float2 v = make_float2(O[mi][nj][h*2] * inv, O[mi][nj][h*2+1] * inv);
                *(float2*)(dst + nj * 8 + (lane & 3) * 2) = v;
            }
        }
}

// ---------------------------------------------------------------------------
extern "C" void kernel_launch(void* const* d_in, const int* in_sizes, int n_in,
                              void* d_out, int out_size)
{
    const float* x  = (const float*)d_in[0];
    const float* Wq = (const float*)d_in[1];
    const float* Wk = (const float*)d_in[2];
    const float* Wv = (const float*)d_in[3];
    const float* Wo = (const float*)d_in[4];
    float* out = (float*)d_out;

    float *q, *k, *att;
    __half *xh, *wh, *qh, *kh, *vh;
    cudaGetSymbolAddress((void**)&q,   g_q);
    cudaGetSymbolAddress((void**)&k,   g_k);
    cudaGetSymbolAddress((void**)&att, g_att);
    cudaGetSymbolAddress((void**)&xh,  g_xh);
    cudaGetSymbolAddress((void**)&wh,  g_wh);
    cudaGetSymbolAddress((void**)&qh,  g_qh);
    cudaGetSymbolAddress((void**)&kh,  g_kh);
    cudaGetSymbolAddress((void**)&vh,  g_vh);

    const int M = B_ * T_;   // 4096
    const int NWX = (M * C_) / (256 * 4);
    const int NWW = (C_ * C_) / (256 * 4);

    dim3 gg(C_ / 128, M / 128);   // (8, 32)

    f2h_kernel<<<NWX, 256>>>(x, xh, M * C_);
    f2h_kernel<<<NWW, 256>>>(Wq, wh, C_ * C_);
    gemm_mma<1><<<gg, 256>>>(xh, wh, q, M, C_, C_);
    f2h_kernel<<<NWW, 256>>>(Wk, wh, C_ * C_);
    gemm_mma<1><<<gg, 256>>>(xh, wh, k, M, C_, C_);
    f2h_kernel<<<NWW, 256>>>(Wv, wh, C_ * C_);
    gemm_mma<2><<<gg, 256>>>(xh, wh, (float*)vh, M, C_, C_);

    rope_kernel<<<(B_ * H_ * T_) / 8, 256>>>(q, k, qh, kh);

    int asmem = (128 + 2 * 64 + 2 * 64) * ATS * 2;   // 67584 B
    cudaFuncSetAttribute(attn_mma, cudaFuncAttributeMaxDynamicSharedMemorySize, asmem);
    attn_mma<<<dim3(B_ * H_, T_ / 128), 128, asmem>>>();

    f2h_kernel<<<NWX, 256>>>(att, xh, M * C_);
    f2h_kernel<<<NWW, 256>>>(Wo, wh, C_ * C_);
    gemm_mma<0><<<gg, 256>>>(xh, wh, out, M, C_, C_);
}

// round 5
// speedup vs baseline: 9.1904x; 1.1400x over previous
#include <cuda_runtime.h>
#include <cuda_fp16.h>
#include <math.h>
#include <stdint.h>

#define B_ 2
#define T_ 2048
#define C_ 1024
#define H_ 16
#define D_ 64
#define CC_ (C_*C_)

// Scratch (allocation-free rule: __device__ globals)
__device__ __half g_xh[(size_t)B_*T_*C_];      // fp16 activations (x, then attn out)
__device__ __half g_wh[(size_t)4*CC_];         // fp16 weights: Wq,Wk,Wv,Wo
__device__ __half g_qh[(size_t)B_*H_*T_*D_];
__device__ __half g_kh[(size_t)B_*H_*T_*D_];
__device__ __half g_vh[(size_t)B_*H_*T_*D_];
__device__ float2 g_rope[(size_t)T_*32];       // (cos, sin) per (t, d)

#define QSCALE 0.18033688011112042f   // 0.125 * log2(e)

// ---------------------------------------------------------------------------
// common helpers
// ---------------------------------------------------------------------------
__device__ __forceinline__ void cp_async16(uint32_t dst, const void* src) {
    asm volatile("cp.async.ca.shared.global [%0], [%1], 16;" :: "r"(dst), "l"(src));
}
__device__ __forceinline__ void ldmatrix_x4(uint32_t& r0, uint32_t& r1,
                                            uint32_t& r2, uint32_t& r3, uint32_t a) {
    asm volatile("ldmatrix.sync.aligned.m8n8.x4.shared.b16 {%0,%1,%2,%3}, [%4];"
                 : "=r"(r0), "=r"(r1), "=r"(r2), "=r"(r3) : "r"(a));
}
__device__ __forceinline__ void ldmatrix_x4_t(uint32_t& r0, uint32_t& r1,
                                              uint32_t& r2, uint32_t& r3, uint32_t a) {
    asm volatile("ldmatrix.sync.aligned.m8n8.x4.trans.shared.b16 {%0,%1,%2,%3}, [%4];"
                 : "=r"(r0), "=r"(r1), "=r"(r2), "=r"(r3) : "r"(a));
}
__device__ __forceinline__ void mma16816(float* d, const uint32_t* a, const uint32_t* b) {
    asm volatile("mma.sync.aligned.m16n8k16.row.col.f32.f16.f16.f32 "
                 "{%0,%1,%2,%3}, {%4,%5,%6,%7}, {%8,%9}, {%0,%1,%2,%3};"
                 : "+f"(d[0]), "+f"(d[1]), "+f"(d[2]), "+f"(d[3])
                 : "r"(a[0]), "r"(a[1]), "r"(a[2]), "r"(a[3]), "r"(b[0]), "r"(b[1]));
}
__device__ __forceinline__ uint32_t pack_h2(float a, float b) {
    __half2 h = __floats2half2_rn(a, b);
    return *(uint32_t*)&h;
}

// ---------------------------------------------------------------------------
// fp32 -> fp16 conversion
// ---------------------------------------------------------------------------
__global__ __launch_bounds__(256)
void f2h_kernel(const float* __restrict__ src, __half* __restrict__ dst, int n)
{
    int i = (blockIdx.x * 256 + threadIdx.x) * 4;
    if (i < n) {
        float4 v = *(const float4*)(src + i);
        __half2 a = __floats2half2_rn(v.x, v.y);
        __half2 b = __floats2half2_rn(v.z, v.w);
        uint2 o;
        o.x = *(uint32_t*)&a;
        o.y = *(uint32_t*)&b;
        *(uint2*)(dst + i) = o;
    }
}

// ---------------------------------------------------------------------------
// RoPE cos/sin table: idx = t*32 + d
// ---------------------------------------------------------------------------
__global__ __launch_bounds__(256)
void rope_table_kernel()
{
    int idx = blockIdx.x * 256 + threadIdx.x;   // [0, 65536)
    int t = idx >> 5, d = idx & 31;
    float invf = exp2f(-0.4152410118609203f * (float)d);
    float sn, cs;
    sincosf((float)t * invf, &sn, &cs);
    g_rope[idx] = make_float2(cs, sn);
}

// ---------------------------------------------------------------------------
// HMMA GEMM: Y = Xh @ W^T.  CTA 128x128, 4 warps (warp tile 64x64), BK=32,
// 3-stage cp.async pipeline, 128 threads.
// MODE 0: fp32 row-major Y (out-proj; W = Wbase).
// MODE 1: QKV fused: z = blockIdx.z selects W slice + destination;
//         z=0 -> RoPE+QSCALE -> g_qh, z=1 -> RoPE -> g_kh, z=2 -> g_vh (all fp16).
// ---------------------------------------------------------------------------
#define SSTR 40                         // smem row stride in halves
#define STG_HALVES (2 * 128 * SSTR)     // A + B per stage
#define GEMM_SMEM (3 * STG_HALVES * 2)  // 61440 B

template <int MODE>
__global__ __launch_bounds__(128)
void gemm4(const __half* __restrict__ Xh, const __half* __restrict__ Wbase,
           float* __restrict__ Yout, int M, int N, int K)
{
    extern __shared__ __align__(16) __half sm[];

    const int tid  = threadIdx.x;
    const int wid  = tid >> 5;
    const int lane = tid & 31;
    const int m0 = blockIdx.y * 128;
    const int n0 = blockIdx.x * 128;
    const int wm = (wid & 1) * 64;
    const int wn = (wid >> 1) * 64;
    const int z  = (MODE == 1) ? blockIdx.z : 0;
    const __half* W = Wbase + (size_t)z * CC_;

    float acc[4][8][4];
#pragma unroll
    for (int i = 0; i < 4; i++)
#pragma unroll
        for (int j = 0; j < 8; j++)
#pragma unroll
            for (int c = 0; c < 4; c++) acc[i][j][c] = 0.f;

    auto issue_stage = [&](int s, int k0) {
        __half* As = sm + s * STG_HALVES;
        __half* Bs = As + 128 * SSTR;
#pragma unroll
        for (int li = 0; li < 4; li++) {
            int c   = tid + li * 128;
            int row = c >> 2;
            int seg = (c & 3) * 8;
            cp_async16((uint32_t)__cvta_generic_to_shared(&As[row * SSTR + seg]),
                       Xh + (size_t)(m0 + row) * K + k0 + seg);
            cp_async16((uint32_t)__cvta_generic_to_shared(&Bs[row * SSTR + seg]),
                       W + (size_t)(n0 + row) * K + k0 + seg);
        }
        asm volatile("cp.async.commit_group;");
    };

    const int NT = K / 32;
    issue_stage(0, 0);
    issue_stage(1, 32);

    for (int kt = 0; kt < NT; kt++) {
        const int s = kt % 3;
        if (kt + 1 < NT) asm volatile("cp.async.wait_group 1;");
        else             asm volatile("cp.async.wait_group 0;");
        __syncthreads();

        __half* As = sm + s * STG_HALVES;
        __half* Bs = As + 128 * SSTR;

#pragma unroll
        for (int kk = 0; kk < 2; kk++) {
            uint32_t af[4][4];
#pragma unroll
            for (int mi = 0; mi < 4; mi++) {
                uint32_t a = (uint32_t)__cvta_generic_to_shared(
                    &As[(wm + mi * 16 + (lane & 15)) * SSTR + kk * 16 + ((lane >> 4) << 3)]);
                ldmatrix_x4(af[mi][0], af[mi][1], af[mi][2], af[mi][3], a);
            }
            uint32_t bf[8][2];
#pragma unroll
            for (int nb = 0; nb < 4; nb++) {
                uint32_t r0, r1, r2, r3;
                uint32_t a = (uint32_t)__cvta_generic_to_shared(
                    &Bs[(wn + nb * 16 + (lane & 7) + ((lane >> 4) << 3)) * SSTR
                        + kk * 16 + ((lane >> 3) & 1) * 8]);
                ldmatrix_x4(r0, r1, r2, r3, a);
                bf[nb * 2 + 0][0] = r0; bf[nb * 2 + 0][1] = r1;
                bf[nb * 2 + 1][0] = r2; bf[nb * 2 + 1][1] = r3;
            }
#pragma unroll
            for (int mi = 0; mi < 4; mi++)
#pragma unroll
                for (int ni = 0; ni < 8; ni++)
                    mma16816(acc[mi][ni], af[mi], bf[ni]);
        }
        __syncthreads();
        if (kt + 2 < NT) issue_stage((kt + 2) % 3, (kt + 2) * 32);
    }

    // ---- epilogue ----
    if (MODE == 0) {
#pragma unroll
        for (int mi = 0; mi < 4; mi++)
#pragma unroll
            for (int h = 0; h < 2; h++) {
                int row = m0 + wm + mi * 16 + (lane >> 2) + h * 8;
#pragma unroll
                for (int ni = 0; ni < 8; ni++) {
                    int col = n0 + wn + ni * 8 + (lane & 3) * 2;
                    *(float2*)(Yout + (size_t)row * N + col) =
                        make_float2(acc[mi][ni][h * 2], acc[mi][ni][h * 2 + 1]);
                }
            }
    } else {
        const int hh = (n0 + wn) >> 6;       // one head per warp tile
#pragma unroll
        for (int mi = 0; mi < 4; mi++)
#pragma unroll
            for (int h = 0; h < 2; h++) {
                int row = m0 + wm + mi * 16 + (lane >> 2) + h * 8;
                int b = row >> 11;
                int t = row & (T_ - 1);
                size_t base = (((size_t)b * H_ + hh) * T_ + t) * D_;
                if (z == 2) {
#pragma unroll
                    for (int nj = 0; nj < 8; nj++) {
                        int d = nj * 8 + (lane & 3) * 2;
                        *(uint32_t*)(g_vh + base + d) =
                            pack_h2(acc[mi][nj][h * 2], acc[mi][nj][h * 2 + 1]);
                    }
                } else {
                    __half* dst = z ? g_kh : g_qh;
                    const float qs = z ? 1.f : QSCALE;
#pragma unroll
                    for (int nj = 0; nj < 4; nj++) {
                        float vlo[2], vhi[2];
#pragma unroll
                        for (int e = 0; e < 2; e++) {
                            int d = nj * 8 + (lane & 3) * 2 + e;     // [0,32)
                            float lo = acc[mi][nj][h * 2 + e];
                            float hi = acc[mi][nj + 4][h * 2 + e];
                            float2 cs = g_rope[t * 32 + d];
                            vlo[e] = (lo * cs.x - hi * cs.y) * qs;
                            vhi[e] = (hi * cs.x + lo * cs.y) * qs;
                        }
                        int d0 = nj * 8 + (lane & 3) * 2;
                        *(uint32_t*)(dst + base + d0)      = pack_h2(vlo[0], vlo[1]);
                        *(uint32_t*)(dst + base + d0 + 32) = pack_h2(vhi[0], vhi[1]);
                    }
                }
            }
    }
}

// ---------------------------------------------------------------------------
// Tensor-core causal flash attention (fp16 in, fp32 accum), writes fp16 [B,T,C].
// CTA: 128 q-rows, 4 warps, KV tiles of 64.  grid (B*H, T/128), 128 threads.
// ---------------------------------------------------------------------------
#define ATS 88

__global__ __launch_bounds__(128, 1)
void attn_mma()
{
    extern __shared__ __half ash[];
    __half (*Qs)[ATS] = (__half(*)[ATS])ash;
    __half (*Ks)[64][ATS] = (__half(*)[64][ATS])(ash + 128 * ATS);
    __half (*Vs)[64][ATS] = (__half(*)[64][ATS])(ash + (128 + 2*64) * ATS);

    const int bh = blockIdx.x, qt = blockIdx.y;
    const int tid = threadIdx.x, wid = tid >> 5, lane = tid & 31;

    const __half* Qg = g_qh + ((size_t)bh * T_ + qt * 128) * D_;
    const __half* Kg = g_kh + (size_t)bh * T_ * D_;
    const __half* Vg = g_vh + (size_t)bh * T_ * D_;

#pragma unroll
    for (int i = 0; i < 8; i++) {
        int c = tid + i * 128;
        int row = c >> 3, seg = c & 7;
        *(uint4*)&Qs[row][seg * 8] = *(const uint4*)(Qg + row * 64 + seg * 8);
    }
    __syncthreads();

    uint32_t qa[2][4][4];
#pragma unroll
    for (int mi = 0; mi < 2; mi++)
#pragma unroll
        for (int t = 0; t < 4; t++) {
            uint32_t a = (uint32_t)__cvta_generic_to_shared(
                &Qs[wid * 32 + mi * 16 + ((lane >> 3) & 1) * 8 + (lane & 7)]
                   [t * 16 + (lane >> 4) * 8]);
            ldmatrix_x4(qa[mi][t][0], qa[mi][t][1], qa[mi][t][2], qa[mi][t][3], a);
        }

    float O[2][8][4];
#pragma unroll
    for (int mi = 0; mi < 2; mi++)
#pragma unroll
        for (int nj = 0; nj < 8; nj++)
#pragma unroll
            for (int c = 0; c < 4; c++) O[mi][nj][c] = 0.f;
    float mrow[2][2] = {{-INFINITY, -INFINITY}, {-INFINITY, -INFINITY}};
    float lrow[2][2] = {{0.f, 0.f}, {0.f, 0.f}};

    const int nkt = 2 * qt + 2;

    auto issue = [&](int s, int kt) {
#pragma unroll
        for (int i = 0; i < 8; i++) {
            int c = tid + i * 128;
            int isV = c >> 9, cc = c & 511, row = cc >> 3, seg = cc & 7;
            const __half* src = (isV ? Vg : Kg) + (size_t)(kt * 64 + row) * 64 + seg * 8;
            uint32_t dst = (uint32_t)__cvta_generic_to_shared(
                isV ? &Vs[s][row][seg * 8] : &Ks[s][row][seg * 8]);
            cp_async16(dst, src);
        }
        asm volatile("cp.async.commit_group;");
    };
    issue(0, 0);

    for (int kt = 0; kt < nkt; kt++) {
        const int s = kt & 1;
        if (kt + 1 < nkt) {
            issue(s ^ 1, kt + 1);
            asm volatile("cp.async.wait_group 1;");
        } else {
            asm volatile("cp.async.wait_group 0;");
        }
        __syncthreads();

        bool active = (qt * 128 + wid * 32 + 31) >= kt * 64;
        if (active) {
            float S[2][8][4];
#pragma unroll
            for (int mi = 0; mi < 2; mi++)
#pragma unroll
                for (int nj = 0; nj < 8; nj++)
#pragma unroll
                    for (int c = 0; c < 4; c++) S[mi][nj][c] = 0.f;

#pragma unroll
            for (int t = 0; t < 4; t++) {
                uint32_t bf[8][2];
#pragma unroll
                for (int jp = 0; jp < 4; jp++) {
                    uint32_t a = (uint32_t)__cvta_generic_to_shared(
                        &Ks[s][jp * 16 + ((lane >> 4) & 1) * 8 + (lane & 7)]
                            [t * 16 + ((lane >> 3) & 1) * 8]);
                    ldmatrix_x4(bf[2*jp][0], bf[2*jp][1], bf[2*jp+1][0], bf[2*jp+1][1], a);
                }
#pragma unroll
                for (int mi = 0; mi < 2; mi++)
#pragma unroll
                    for (int nj = 0; nj < 8; nj++)
                        mma16816(S[mi][nj], qa[mi][t], bf[nj]);
            }

            if (kt >= 2 * qt) {
#pragma unroll
                for (int mi = 0; mi < 2; mi++)
#pragma unroll
                    for (int h = 0; h < 2; h++) {
                        int row = qt * 128 + wid * 32 + mi * 16 + (lane >> 2) + h * 8;
#pragma unroll
                        for (int nj = 0; nj < 8; nj++)
#pragma unroll
                            for (int e = 0; e < 2; e++) {
                                int key = kt * 64 + nj * 8 + (lane & 3) * 2 + e;
                                if (key > row) S[mi][nj][h * 2 + e] = -1e30f;
                            }
                    }
            }

            float al[2][2];
#pragma unroll
            for (int mi = 0; mi < 2; mi++)
#pragma unroll
                for (int h = 0; h < 2; h++) {
                    float rm = -1e30f;
#pragma unroll
                    for (int nj = 0; nj < 8; nj++)
                        rm = fmaxf(rm, fmaxf(S[mi][nj][h*2], S[mi][nj][h*2+1]));
                    rm = fmaxf(rm, __shfl_xor_sync(0xffffffffu, rm, 1));
                    rm = fmaxf(rm, __shfl_xor_sync(0xffffffffu, rm, 2));
                    float mn = fmaxf(mrow[mi][h], rm);
                    float alpha = exp2f(mrow[mi][h] - mn);
                    mrow[mi][h] = mn;
                    float ps = 0.f;
#pragma unroll
                    for (int nj = 0; nj < 8; nj++) {
                        float p0 = exp2f(S[mi][nj][h*2]   - mn);
                        float p1 = exp2f(S[mi][nj][h*2+1] - mn);
                        S[mi][nj][h*2]   = p0;
                        S[mi][nj][h*2+1] = p1;
                        ps += p0 + p1;
                    }
                    ps += __shfl_xor_sync(0xffffffffu, ps, 1);
                    ps += __shfl_xor_sync(0xffffffffu, ps, 2);
                    lrow[mi][h] = lrow[mi][h] * alpha + ps;
                    al[mi][h] = alpha;
                }
#pragma unroll
            for (int mi = 0; mi < 2; mi++)
#pragma unroll
                for (int nj = 0; nj < 8; nj++) {
                    O[mi][nj][0] *= al[mi][0];
                    O[mi][nj][1] *= al[mi][0];
                    O[mi][nj][2] *= al[mi][1];
                    O[mi][nj][3] *= al[mi][1];
                }

#pragma unroll
            for (int t = 0; t < 4; t++) {
                uint32_t bv[8][2];
#pragma unroll
                for (int jp = 0; jp < 4; jp++) {
                    uint32_t a = (uint32_t)__cvta_generic_to_shared(
                        &Vs[s][t * 16 + ((lane >> 3) & 1) * 8 + (lane & 7)]
                            [(2 * jp + ((lane >> 4) & 1)) * 8]);
                    ldmatrix_x4_t(bv[2*jp][0], bv[2*jp][1], bv[2*jp+1][0], bv[2*jp+1][1], a);
                }
#pragma unroll
                for (int mi = 0; mi < 2; mi++) {
                    uint32_t pa[4];
                    pa[0] = pack_h2(S[mi][2*t][0],   S[mi][2*t][1]);
                    pa[1] = pack_h2(S[mi][2*t][2],   S[mi][2*t][3]);
                    pa[2] = pack_h2(S[mi][2*t+1][0], S[mi][2*t+1][1]);
                    pa[3] = pack_h2(S[mi][2*t+1][2], S[mi][2*t+1][3]);
#pragma unroll
                    for (int nj = 0; nj < 8; nj++)
                        mma16816(O[mi][nj], pa, bv[nj]);
                }
            }
        }
        __syncthreads();
    }

    // epilogue: normalize, write fp16 into g_xh [B,T,C]
    const int b = bh >> 4, hh = bh & (H_ - 1);
#pragma unroll
    for (int mi = 0; mi < 2; mi++)
#pragma unroll
        for (int h = 0; h < 2; h++) {
            float inv = 1.f / lrow[mi][h];
            int row = qt * 128 + wid * 32 + mi * 16 + (lane >> 2) + h * 8;
            __half* dst = g_xh + ((size_t)(b * T_ + row)) * C_ + hh * 64;
#pragma unroll
            for (int nj = 0; nj < 8; nj++)
                *(uint32_t*)(dst + nj * 8 + (lane & 3) * 2) =
                    pack_h2(O[mi][nj][h*2] * inv, O[mi][nj][h*2+1] * inv);
        }
}

// ---------------------------------------------------------------------------
extern "C" void kernel_launch(void* const* d_in, const int* in_sizes, int n_in,
                              void* d_out, int out_size)
{
    const float* x  = (const float*)d_in[0];
    const float* Wq = (const float*)d_in[1];
    const float* Wk = (const float*)d_in[2];
    const float* Wv = (const float*)d_in[3];
    const float* Wo = (const float*)d_in[4];
    float* out = (float*)d_out;

    __half *xh, *wh;
    cudaGetSymbolAddress((void**)&xh, g_xh);
    cudaGetSymbolAddress((void**)&wh, g_wh);

    const int M = B_ * T_;   // 4096
    const int NWX = (M * C_) / (256 * 4);
    const int NWW = CC_ / (256 * 4);

    cudaFuncSetAttribute(gemm4<0>, cudaFuncAttributeMaxDynamicSharedMemorySize, GEMM_SMEM);
    cudaFuncSetAttribute(gemm4<1>, cudaFuncAttributeMaxDynamicSharedMemorySize, GEMM_SMEM);

    f2h_kernel<<<NWX, 256>>>(x, xh, M * C_);
    f2h_kernel<<<NWW, 256>>>(Wq, wh + 0 * CC_, CC_);
    f2h_kernel<<<NWW, 256>>>(Wk, wh + 1 * CC_, CC_);
    f2h_kernel<<<NWW, 256>>>(Wv, wh + 2 * CC_, CC_);
    f2h_kernel<<<NWW, 256>>>(Wo, wh + 3 * CC_, CC_);
    rope_table_kernel<<<(T_ * 32) / 256, 256>>>();

    gemm4<1><<<dim3(C_ / 128, M / 128, 3), 128, GEMM_SMEM>>>(xh, wh, nullptr, M, C_, C_);

    int asmem = (128 + 2 * 64 + 2 * 64) * ATS * 2;   // 67584 B
    cudaFuncSetAttribute(attn_mma, cudaFuncAttributeMaxDynamicSharedMemorySize, asmem);
    attn_mma<<<dim3(B_ * H_, T_ / 128), 128, asmem>>>();

    gemm4<0><<<dim3(C_ / 128, M / 128), 128, GEMM_SMEM>>>(xh, wh + 3 * CC_, out, M, C_, C_);
}

// round 6
// speedup vs baseline: 11.4459x; 1.2454x over previous
#include <cuda_runtime.h>
#include <cuda_fp16.h>
#include <math.h>
#include <stdint.h>

#define B_ 2
#define T_ 2048
#define C_ 1024
#define H_ 16
#define D_ 64
#define CC_ (C_*C_)

// Scratch (allocation-free rule: __device__ globals)
__device__ __half g_xh[(size_t)B_*T_*C_];      // fp16 activations (x, then attn out)
__device__ __half g_wh[(size_t)4*CC_];         // fp16 weights: Wq,Wk,Wv,Wo
__device__ __half g_qh[(size_t)B_*H_*T_*D_];
__device__ __half g_kh[(size_t)B_*H_*T_*D_];
__device__ __half g_vh[(size_t)B_*H_*T_*D_];
__device__ float2 g_rope[(size_t)T_*32];       // (cos, sin) per (t, d)

#define QSCALE 0.18033688011112042f   // 0.125 * log2(e)

// ---------------------------------------------------------------------------
// common helpers
// ---------------------------------------------------------------------------
__device__ __forceinline__ void cp_async16(uint32_t dst, const void* src) {
    asm volatile("cp.async.ca.shared.global [%0], [%1], 16;" :: "r"(dst), "l"(src));
}
__device__ __forceinline__ void ldmatrix_x4(uint32_t& r0, uint32_t& r1,
                                            uint32_t& r2, uint32_t& r3, uint32_t a) {
    asm volatile("ldmatrix.sync.aligned.m8n8.x4.shared.b16 {%0,%1,%2,%3}, [%4];"
                 : "=r"(r0), "=r"(r1), "=r"(r2), "=r"(r3) : "r"(a));
}
__device__ __forceinline__ void ldmatrix_x4_t(uint32_t& r0, uint32_t& r1,
                                              uint32_t& r2, uint32_t& r3, uint32_t a) {
    asm volatile("ldmatrix.sync.aligned.m8n8.x4.trans.shared.b16 {%0,%1,%2,%3}, [%4];"
                 : "=r"(r0), "=r"(r1), "=r"(r2), "=r"(r3) : "r"(a));
}
__device__ __forceinline__ void mma16816(float* d, const uint32_t* a, const uint32_t* b) {
    asm volatile("mma.sync.aligned.m16n8k16.row.col.f32.f16.f16.f32 "
                 "{%0,%1,%2,%3}, {%4,%5,%6,%7}, {%8,%9}, {%0,%1,%2,%3};"
                 : "+f"(d[0]), "+f"(d[1]), "+f"(d[2]), "+f"(d[3])
                 : "r"(a[0]), "r"(a[1]), "r"(a[2]), "r"(a[3]), "r"(b[0]), "r"(b[1]));
}
__device__ __forceinline__ uint32_t pack_h2(float a, float b) {
    __half2 h = __floats2half2_rn(a, b);
    return *(uint32_t*)&h;
}

// ---------------------------------------------------------------------------
// Fused prep kernel: x->fp16, 4 weights->fp16, RoPE table. One launch.
// blocks [0, NBX):            x convert        (1024 elts/block)
// blocks [NBX, NBX+4*NBW):    weight converts
// blocks [NBX+4*NBW, +256):   rope table
// ---------------------------------------------------------------------------
#define NBX ((B_*T_*C_) / 1024)     // 4096
#define NBW (CC_ / 1024)            // 1024
#define NBPREP (NBX + 4*NBW + 256)  // 8448

__global__ __launch_bounds__(256)
void prep_kernel(const float* __restrict__ x,
                 const float* __restrict__ Wq, const float* __restrict__ Wk,
                 const float* __restrict__ Wv, const float* __restrict__ Wo)
{
    int bid = blockIdx.x;
    if (bid < NBX + 4 * NBW) {
        const float* src;
        __half* dst;
        int lb;
        if (bid < NBX) {
            src = x; dst = g_xh; lb = bid;
        } else {
            int w = (bid - NBX) >> 10;          // which weight
            lb = (bid - NBX) & 1023;
            src = (w == 0) ? Wq : (w == 1) ? Wk : (w == 2) ? Wv : Wo;
            dst = g_wh + (size_t)w * CC_;
        }
        int i = (lb * 256 + threadIdx.x) * 4;
        float4 v = *(const float4*)(src + i);
        __half2 a = __floats2half2_rn(v.x, v.y);
        __half2 b = __floats2half2_rn(v.z, v.w);
        uint2 o;
        o.x = *(uint32_t*)&a;
        o.y = *(uint32_t*)&b;
        *(uint2*)(dst + i) = o;
    } else {
        int idx = (bid - NBX - 4 * NBW) * 256 + threadIdx.x;   // [0, 65536)
        int t = idx >> 5, d = idx & 31;
        float invf = exp2f(-0.4152410118609203f * (float)d);
        float sn, cs;
        sincosf((float)t * invf, &sn, &cs);
        g_rope[idx] = make_float2(cs, sn);
    }
}

// ---------------------------------------------------------------------------
// HMMA GEMM: Y = Xh @ W^T.  CTA 128x128, 4 warps (warp tile 64x64), BK=32,
// 3-stage cp.async pipeline, 128 threads, 2 CTAs/SM.
// MODE 0: fp32 row-major Y (out-proj; W = Wbase).
// MODE 1: QKV fused: z = blockIdx.z selects W slice + destination;
//         z=0 -> RoPE+QSCALE -> g_qh, z=1 -> RoPE -> g_kh, z=2 -> g_vh (all fp16).
// ---------------------------------------------------------------------------
#define SSTR 40                         // smem row stride in halves
#define STG_HALVES (2 * 128 * SSTR)     // A + B per stage
#define GEMM_SMEM (3 * STG_HALVES * 2)  // 61440 B

template <int MODE>
__global__ __launch_bounds__(128, 2)
void gemm4(const __half* __restrict__ Xh, const __half* __restrict__ Wbase,
           float* __restrict__ Yout, int M, int N, int K)
{
    extern __shared__ __align__(16) __half sm[];

    const int tid  = threadIdx.x;
    const int wid  = tid >> 5;
    const int lane = tid & 31;
    const int m0 = blockIdx.y * 128;
    const int n0 = blockIdx.x * 128;
    const int wm = (wid & 1) * 64;
    const int wn = (wid >> 1) * 64;
    const int z  = (MODE == 1) ? blockIdx.z : 0;
    const __half* W = Wbase + (size_t)z * CC_;

    float acc[4][8][4];
#pragma unroll
    for (int i = 0; i < 4; i++)
#pragma unroll
        for (int j = 0; j < 8; j++)
#pragma unroll
            for (int c = 0; c < 4; c++) acc[i][j][c] = 0.f;

    auto issue_stage = [&](int s, int k0) {
        __half* As = sm + s * STG_HALVES;
        __half* Bs = As + 128 * SSTR;
#pragma unroll
        for (int li = 0; li < 4; li++) {
            int c   = tid + li * 128;
            int row = c >> 2;
            int seg = (c & 3) * 8;
            cp_async16((uint32_t)__cvta_generic_to_shared(&As[row * SSTR + seg]),
                       Xh + (size_t)(m0 + row) * K + k0 + seg);
            cp_async16((uint32_t)__cvta_generic_to_shared(&Bs[row * SSTR + seg]),
                       W + (size_t)(n0 + row) * K + k0 + seg);
        }
        asm volatile("cp.async.commit_group;");
    };

    const int NT = K / 32;
    issue_stage(0, 0);
    issue_stage(1, 32);

    for (int kt = 0; kt < NT; kt++) {
        const int s = kt % 3;
        if (kt + 1 < NT) asm volatile("cp.async.wait_group 1;");
        else             asm volatile("cp.async.wait_group 0;");
        __syncthreads();

        __half* As = sm + s * STG_HALVES;
        __half* Bs = As + 128 * SSTR;

#pragma unroll
        for (int kk = 0; kk < 2; kk++) {
            uint32_t af[4][4];
#pragma unroll
            for (int mi = 0; mi < 4; mi++) {
                uint32_t a = (uint32_t)__cvta_generic_to_shared(
                    &As[(wm + mi * 16 + (lane & 15)) * SSTR + kk * 16 + ((lane >> 4) << 3)]);
                ldmatrix_x4(af[mi][0], af[mi][1], af[mi][2], af[mi][3], a);
            }
            uint32_t bf[8][2];
#pragma unroll
            for (int nb = 0; nb < 4; nb++) {
                uint32_t r0, r1, r2, r3;
                uint32_t a = (uint32_t)__cvta_generic_to_shared(
                    &Bs[(wn + nb * 16 + (lane & 7) + ((lane >> 4) << 3)) * SSTR
                        + kk * 16 + ((lane >> 3) & 1) * 8]);
                ldmatrix_x4(r0, r1, r2, r3, a);
                bf[nb * 2 + 0][0] = r0; bf[nb * 2 + 0][1] = r1;
                bf[nb * 2 + 1][0] = r2; bf[nb * 2 + 1][1] = r3;
            }
#pragma unroll
            for (int mi = 0; mi < 4; mi++)
#pragma unroll
                for (int ni = 0; ni < 8; ni++)
                    mma16816(acc[mi][ni], af[mi], bf[ni]);
        }
        __syncthreads();
        if (kt + 2 < NT) issue_stage((kt + 2) % 3, (kt + 2) * 32);
    }

    // ---- epilogue ----
    if (MODE == 0) {
#pragma unroll
        for (int mi = 0; mi < 4; mi++)
#pragma unroll
            for (int h = 0; h < 2; h++) {
                int row = m0 + wm + mi * 16 + (lane >> 2) + h * 8;
#pragma unroll
                for (int ni = 0; ni < 8; ni++) {
                    int col = n0 + wn + ni * 8 + (lane & 3) * 2;
                    *(float2*)(Yout + (size_t)row * N + col) =
                        make_float2(acc[mi][ni][h * 2], acc[mi][ni][h * 2 + 1]);
                }
            }
    } else {
        const int hh = (n0 + wn) >> 6;       // one head per warp tile
#pragma unroll
        for (int mi = 0; mi < 4; mi++)
#pragma unroll
            for (int h = 0; h < 2; h++) {
                int row = m0 + wm + mi * 16 + (lane >> 2) + h * 8;
                int b = row >> 11;
                int t = row & (T_ - 1);
                size_t base = (((size_t)b * H_ + hh) * T_ + t) * D_;
                if (z == 2) {
#pragma unroll
                    for (int nj = 0; nj < 8; nj++) {
                        int d = nj * 8 + (lane & 3) * 2;
                        *(uint32_t*)(g_vh + base + d) =
                            pack_h2(acc[mi][nj][h * 2], acc[mi][nj][h * 2 + 1]);
                    }
                } else {
                    __half* dst = z ? g_kh : g_qh;
                    const float qs = z ? 1.f : QSCALE;
#pragma unroll
                    for (int nj = 0; nj < 4; nj++) {
                        float vlo[2], vhi[2];
#pragma unroll
                        for (int e = 0; e < 2; e++) {
                            int d = nj * 8 + (lane & 3) * 2 + e;     // [0,32)
                            float lo = acc[mi][nj][h * 2 + e];
                            float hi = acc[mi][nj + 4][h * 2 + e];
                            float2 cs = g_rope[t * 32 + d];
                            vlo[e] = (lo * cs.x - hi * cs.y) * qs;
                            vhi[e] = (hi * cs.x + lo * cs.y) * qs;
                        }
                        int d0 = nj * 8 + (lane & 3) * 2;
                        *(uint32_t*)(dst + base + d0)      = pack_h2(vlo[0], vlo[1]);
                        *(uint32_t*)(dst + base + d0 + 32) = pack_h2(vhi[0], vhi[1]);
                    }
                }
            }
    }
}

// ---------------------------------------------------------------------------
// Tensor-core causal flash attention (fp16 in, fp32 accum), writes fp16 [B,T,C].
// CTA: 128 q-rows, 4 warps, KV tiles of 64.  grid (B*H, T/128), 128 threads.
// Heavy q-tiles scheduled first (qt = 15 - blockIdx.y).
// ---------------------------------------------------------------------------
#define ATS 72   // 144B stride: 16B-aligned, ldmatrix rows hit disjoint bank quads

__global__ __launch_bounds__(128)
void attn_mma()
{
    extern __shared__ __half ash[];
    __half (*Qs)[ATS] = (__half(*)[ATS])ash;
    __half (*Ks)[64][ATS] = (__half(*)[64][ATS])(ash + 128 * ATS);
    __half (*Vs)[64][ATS] = (__half(*)[64][ATS])(ash + (128 + 2*64) * ATS);

    const int bh = blockIdx.x;
    const int qt = (gridDim.y - 1) - blockIdx.y;   // heavy tiles first
    const int tid = threadIdx.x, wid = tid >> 5, lane = tid & 31;

    const __half* Qg = g_qh + ((size_t)bh * T_ + qt * 128) * D_;
    const __half* Kg = g_kh + (size_t)bh * T_ * D_;
    const __half* Vg = g_vh + (size_t)bh * T_ * D_;

#pragma unroll
    for (int i = 0; i < 8; i++) {
        int c = tid + i * 128;
        int row = c >> 3, seg = c & 7;
        *(uint4*)&Qs[row][seg * 8] = *(const uint4*)(Qg + row * 64 + seg * 8);
    }
    __syncthreads();

    uint32_t qa[2][4][4];
#pragma unroll
    for (int mi = 0; mi < 2; mi++)
#pragma unroll
        for (int t = 0; t < 4; t++) {
            uint32_t a = (uint32_t)__cvta_generic_to_shared(
                &Qs[wid * 32 + mi * 16 + ((lane >> 3) & 1) * 8 + (lane & 7)]
                   [t * 16 + (lane >> 4) * 8]);
            ldmatrix_x4(qa[mi][t][0], qa[mi][t][1], qa[mi][t][2], qa[mi][t][3], a);
        }

    float O[2][8][4];
#pragma unroll
    for (int mi = 0; mi < 2; mi++)
#pragma unroll
        for (int nj = 0; nj < 8; nj++)
#pragma unroll
            for (int c = 0; c < 4; c++) O[mi][nj][c] = 0.f;
    float mrow[2][2] = {{-INFINITY, -INFINITY}, {-INFINITY, -INFINITY}};
    float lrow[2][2] = {{0.f, 0.f}, {0.f, 0.f}};

    const int nkt = 2 * qt + 2;

    auto issue = [&](int s, int kt) {
#pragma unroll
        for (int i = 0; i < 8; i++) {
            int c = tid + i * 128;
            int isV = c >> 9, cc = c & 511, row = cc >> 3, seg = cc & 7;
            const __half* src = (isV ? Vg : Kg) + (size_t)(kt * 64 + row) * 64 + seg * 8;
            uint32_t dst = (uint32_t)__cvta_generic_to_shared(
                isV ? &Vs[s][row][seg * 8] : &Ks[s][row][seg * 8]);
            cp_async16(dst, src);
        }
        asm volatile("cp.async.commit_group;");
    };
    issue(0, 0);

    for (int kt = 0; kt < nkt; kt++) {
        const int s = kt & 1;
        if (kt + 1 < nkt) {
            issue(s ^ 1, kt + 1);
            asm volatile("cp.async.wait_group 1;");
        } else {
            asm volatile("cp.async.wait_group 0;");
        }
        __syncthreads();

        bool active = (qt * 128 + wid * 32 + 31) >= kt * 64;
        if (active) {
            float S[2][8][4];
#pragma unroll
            for (int mi = 0; mi < 2; mi++)
#pragma unroll
                for (int nj = 0; nj < 8; nj++)
#pragma unroll
                    for (int c = 0; c < 4; c++) S[mi][nj][c] = 0.f;

#pragma unroll
            for (int t = 0; t < 4; t++) {
                uint32_t bf[8][2];
#pragma unroll
                for (int jp = 0; jp < 4; jp++) {
                    uint32_t a = (uint32_t)__cvta_generic_to_shared(
                        &Ks[s][jp * 16 + ((lane >> 4) & 1) * 8 + (lane & 7)]
                            [t * 16 + ((lane >> 3) & 1) * 8]);
                    ldmatrix_x4(bf[2*jp][0], bf[2*jp][1], bf[2*jp+1][0], bf[2*jp+1][1], a);
                }
#pragma unroll
                for (int mi = 0; mi < 2; mi++)
#pragma unroll
                    for (int nj = 0; nj < 8; nj++)
                        mma16816(S[mi][nj], qa[mi][t], bf[nj]);
            }

            if (kt >= 2 * qt) {
#pragma unroll
                for (int mi = 0; mi < 2; mi++)
#pragma unroll
                    for (int h = 0; h < 2; h++) {
                        int row = qt * 128 + wid * 32 + mi * 16 + (lane >> 2) + h * 8;
#pragma unroll
                        for (int nj = 0; nj < 8; nj++)
#pragma unroll
                            for (int e = 0; e < 2; e++) {
                                int key = kt * 64 + nj * 8 + (lane & 3) * 2 + e;
                                if (key > row) S[mi][nj][h * 2 + e] = -1e30f;
                            }
                    }
            }

            float al[2][2];
#pragma unroll
            for (int mi = 0; mi < 2; mi++)
#pragma unroll
                for (int h = 0; h < 2; h++) {
                    float rm = -1e30f;
#pragma unroll
                    for (int nj = 0; nj < 8; nj++)
                        rm = fmaxf(rm, fmaxf(S[mi][nj][h*2], S[mi][nj][h*2+1]));
                    rm = fmaxf(rm, __shfl_xor_sync(0xffffffffu, rm, 1));
                    rm = fmaxf(rm, __shfl_xor_sync(0xffffffffu, rm, 2));
                    float mn = fmaxf(mrow[mi][h], rm);
                    float alpha = exp2f(mrow[mi][h] - mn);
                    mrow[mi][h] = mn;
                    float ps = 0.f;
#pragma unroll
                    for (int nj = 0; nj < 8; nj++) {
                        float p0 = exp2f(S[mi][nj][h*2]   - mn);
                        float p1 = exp2f(S[mi][nj][h*2+1] - mn);
                        S[mi][nj][h*2]   = p0;
                        S[mi][nj][h*2+1] = p1;
                        ps += p0 + p1;
                    }
                    ps += __shfl_xor_sync(0xffffffffu, ps, 1);
                    ps += __shfl_xor_sync(0xffffffffu, ps, 2);
                    lrow[mi][h] = lrow[mi][h] * alpha + ps;
                    al[mi][h] = alpha;
                }
#pragma unroll
            for (int mi = 0; mi < 2; mi++)
#pragma unroll
                for (int nj = 0; nj < 8; nj++) {
                    O[mi][nj][0] *= al[mi][0];
                    O[mi][nj][1] *= al[mi][0];
                    O[mi][nj][2] *= al[mi][1];
                    O[mi][nj][3] *= al[mi][1];
                }

#pragma unroll
            for (int t = 0; t < 4; t++) {
                uint32_t bv[8][2];
#pragma unroll
                for (int jp = 0; jp < 4; jp++) {
                    uint32_t a = (uint32_t)__cvta_generic_to_shared(
                        &Vs[s][t * 16 + ((lane >> 3) & 1) * 8 + (lane & 7)]
                            [(2 * jp + ((lane >> 4) & 1)) * 8]);
                    ldmatrix_x4_t(bv[2*jp][0], bv[2*jp][1], bv[2*jp+1][0], bv[2*jp+1][1], a);
                }
#pragma unroll
                for (int mi = 0; mi < 2; mi++) {
                    uint32_t pa[4];
                    pa[0] = pack_h2(S[mi][2*t][0],   S[mi][2*t][1]);
                    pa[1] = pack_h2(S[mi][2*t][2],   S[mi][2*t][3]);
                    pa[2] = pack_h2(S[mi][2*t+1][0], S[mi][2*t+1][1]);
                    pa[3] = pack_h2(S[mi][2*t+1][2], S[mi][2*t+1][3]);
#pragma unroll
                    for (int nj = 0; nj < 8; nj++)
                        mma16816(O[mi][nj], pa, bv[nj]);
                }
            }
        }
        __syncthreads();
    }

    // epilogue: normalize, write fp16 into g_xh [B,T,C]
    const int b = bh >> 4, hh = bh & (H_ - 1);
#pragma unroll
    for (int mi = 0; mi < 2; mi++)
#pragma unroll
        for (int h = 0; h < 2; h++) {
            float inv = 1.f / lrow[mi][h];
            int row = qt * 128 + wid * 32 + mi * 16 + (lane >> 2) + h * 8;
            __half* dst = g_xh + ((size_t)(b * T_ + row)) * C_ + hh * 64;
#pragma unroll
            for (int nj = 0; nj < 8; nj++)
                *(uint32_t*)(dst + nj * 8 + (lane & 3) * 2) =
                    pack_h2(O[mi][nj][h*2] * inv, O[mi][nj][h*2+1] * inv);
        }
}

// ---------------------------------------------------------------------------
extern "C" void kernel_launch(void* const* d_in, const int* in_sizes, int n_in,
                              void* d_out, int out_size)
{
    const float* x  = (const float*)d_in[0];
    const float* Wq = (const float*)d_in[1];
    const float* Wk = (const float*)d_in[2];
    const float* Wv = (const float*)d_in[3];
    const float* Wo = (const float*)d_in[4];
    float* out = (float*)d_out;

    __half *xh, *wh;
    cudaGetSymbolAddress((void**)&xh, g_xh);
    cudaGetSymbolAddress((void**)&wh, g_wh);

    const int M = B_ * T_;   // 4096

    cudaFuncSetAttribute(gemm4<0>, cudaFuncAttributeMaxDynamicSharedMemorySize, GEMM_SMEM);
    cudaFuncSetAttribute(gemm4<1>, cudaFuncAttributeMaxDynamicSharedMemorySize, GEMM_SMEM);

    prep_kernel<<<NBPREP, 256>>>(x, Wq, Wk, Wv, Wo);

    gemm4<1><<<dim3(C_ / 128, M / 128, 3), 128, GEMM_SMEM>>>(xh, wh, nullptr, M, C_, C_);

    int asmem = (128 + 2 * 64 + 2 * 64) * ATS * 2;   // 55296 B
    cudaFuncSetAttribute(attn_mma, cudaFuncAttributeMaxDynamicSharedMemorySize, asmem);
    attn_mma<<<dim3(B_ * H_, T_ / 128), 128, asmem>>>();

    gemm4<0><<<dim3(C_ / 128, M / 128), 128, GEMM_SMEM>>>(xh, wh + 3 * CC_, out, M, C_, C_);
}